// round 17
// baseline (speedup 1.0000x reference)
#include <cuda_runtime.h>

#define NGAUSS 2048
#define NCH    32
#define IMH    80
#define IMW    144
#define NPIX   (IMH*IMW)
#define NTILEX (IMW/8)
#define NTILEY (IMH/8)
#define NTILE  (NTILEX*NTILEY)
#define NVIEW  2
#define NSEG   8
#define SEGLEN (NGAUSS/NSEG)
#define NEARP  0.2f
#define DILATE 0.3f
#define ALPHA_MIN (1.0f/255.0f)
#define T_EPS  1e-4f
#define BATCH  256   // == SEGLEN: one cull round per segment

// prep decomposition
#define EPC    32                 // elements ranked per CTA
#define PWARPS 32                 // warps per prep CTA (1024 threads)
#define KRANGE (NGAUSS/PWARPS)    // 64 keys counted per warp

// depth-sorted per-gaussian attrs: [0]={px,py,ca,cb} [1]={cc,op,tz,idx} ; cull={px,py,rx,ry}
__device__ float4 g_sorted[NVIEW][NGAUSS][2];
__device__ float4 g_cull  [NVIEW][NGAUSS];
// segmented compositing scratch
__device__ float  g_T    [NVIEW][NSEG][NPIX];
__device__ float4 g_list0[NVIEW][NSEG][NTILE][SEGLEN];
__device__ float4 g_list1[NVIEW][NSEG][NTILE][SEGLEN];
__device__ int    g_cnt  [NVIEW][NSEG][NTILE];

// ---------------------------------------------------------------------------
// Phase 1: fused projection + enumeration(rank) sort + scatter.
// grid (NVIEW, NGAUSS/EPC) x 1024. Each CTA:
//   - computes ALL 2048 sort keys locally into smem (tz needs one rotation row),
//   - warp w counts keys in range [w*64, (w+1)*64) for ALL 32 elements
//     (lane l owns element l; broadcast smem reads, conflict-free),
//     writing the partial count non-atomically to scnt2[l][w] (33-padded),
//   - threads t<32 fully project their element (registers), reduce the 32
//     partials, and scatter by rank.
// Keys are unique 64-bit (tz_bits<<32)|idx, so rank = #{key_j < key_e} is a
// stable ascending permutation == jnp.argsort. No inter-CTA dependencies.
// ---------------------------------------------------------------------------
__global__ void __launch_bounds__(1024) prep(const float* __restrict__ means,
                                             const float* __restrict__ opac,
                                             const float* __restrict__ scales,
                                             const float* __restrict__ rots,
                                             const float* __restrict__ cam2img,
                                             const float* __restrict__ cam2ego)
{
    const int v    = blockIdx.x;
    const int t    = threadIdx.x;
    const int w    = t >> 5;      // warp id: key range
    const int lane = t & 31;      // element within CTA
    const int ebase = blockIdx.y * EPC;

    __shared__ unsigned long long sk[NGAUSS];
    __shared__ int scnt2[EPC][PWARPS + 1];   // +1 pad: conflict-free reduce

    const float* Km = cam2img + v * 9;
    const float* E  = cam2ego + v * 16;
    const float fx = Km[0], fy = Km[4], cx = Km[2], cy = Km[5];

    const float R00 = E[0], R01 = E[4], R02 = E[8];
    const float R10 = E[1], R11 = E[5], R12 = E[9];
    const float R20 = E[2], R21 = E[6], R22 = E[10];
    const float ex = E[3], ey = E[7], ez = E[11];
    const float Tx = -(R00*ex + R01*ey + R02*ez);
    const float Ty = -(R10*ex + R11*ey + R12*ez);
    const float Tz = -(R20*ex + R21*ey + R22*ez);
    const float tanfovx = (float)IMW * 0.5f / fx;
    const float tanfovy = (float)IMH * 0.5f / fy;

    // ---- all 2048 keys (only tz + validity needed); 2 per thread ----
    for (int i = t; i < NGAUSS; i += 1024) {
        float mx = means[i*3+0], my = means[i*3+1], mz = means[i*3+2];
        float tzk = R20*mx + R21*my + R22*mz + Tz;
        float keyf = (tzk > NEARP) ? tzk : __int_as_float(0x7F800000);  // +inf
        sk[i] = (((unsigned long long)__float_as_uint(keyf)) << 32) | (unsigned)i;
    }
    __syncthreads();

    // ---- full projection of my element (threads t < EPC only) ----
    float4 a0, a1, cu;
    if (t < EPC) {
        const int n = ebase + t;
        float qw = rots[n*4+0], qx = rots[n*4+1], qy = rots[n*4+2], qz = rots[n*4+3];
        float inv = rsqrtf(qw*qw + qx*qx + qy*qy + qz*qz);
        qw *= inv; qx *= inv; qy *= inv; qz *= inv;
        float r00 = 1.f - 2.f*(qy*qy + qz*qz), r01 = 2.f*(qx*qy - qw*qz), r02 = 2.f*(qx*qz + qw*qy);
        float r10 = 2.f*(qx*qy + qw*qz), r11 = 1.f - 2.f*(qx*qx + qz*qz), r12 = 2.f*(qy*qz - qw*qx);
        float r20 = 2.f*(qx*qz - qw*qy), r21 = 2.f*(qy*qz + qw*qx), r22 = 1.f - 2.f*(qx*qx + qy*qy);

        float sx = scales[n*3+0], sy = scales[n*3+1], sz = scales[n*3+2];
        float m00 = r00*sx, m01 = r01*sy, m02 = r02*sz;
        float m10 = r10*sx, m11 = r11*sy, m12 = r12*sz;
        float m20 = r20*sx, m21 = r21*sy, m22 = r22*sz;

        float S00 = m00*m00 + m01*m01 + m02*m02;
        float S01 = m00*m10 + m01*m11 + m02*m12;
        float S02 = m00*m20 + m01*m21 + m02*m22;
        float S11 = m10*m10 + m11*m11 + m12*m12;
        float S12 = m10*m20 + m11*m21 + m12*m22;
        float S22 = m20*m20 + m21*m21 + m22*m22;

        float mx = means[n*3+0], my = means[n*3+1], mz = means[n*3+2];
        float tx = R00*mx + R01*my + R02*mz + Tx;
        float ty = R10*mx + R11*my + R12*mz + Ty;
        float tz = R20*mx + R21*my + R22*mz + Tz;

        bool  valid = tz > NEARP;
        float tzs   = valid ? tz : 1.0f;
        float txtz  = fminf(fmaxf(tx/tzs, -1.3f*tanfovx), 1.3f*tanfovx);
        float tytz  = fminf(fmaxf(ty/tzs, -1.3f*tanfovy), 1.3f*tanfovy);

        float A00 = R00*S00 + R01*S01 + R02*S02;
        float A01 = R00*S01 + R01*S11 + R02*S12;
        float A02 = R00*S02 + R01*S12 + R02*S22;
        float A10 = R10*S00 + R11*S01 + R12*S02;
        float A11 = R10*S01 + R11*S11 + R12*S12;
        float A12 = R10*S02 + R11*S12 + R12*S22;
        float A20 = R20*S00 + R21*S01 + R22*S02;
        float A21 = R20*S01 + R21*S11 + R22*S12;
        float A22 = R20*S02 + R21*S12 + R22*S22;
        float C00 = A00*R00 + A01*R01 + A02*R02;
        float C01 = A00*R10 + A01*R11 + A02*R12;
        float C02 = A00*R20 + A01*R21 + A02*R22;
        float C11 = A10*R10 + A11*R11 + A12*R12;
        float C12 = A10*R20 + A11*R21 + A12*R22;
        float C22 = A20*R20 + A21*R21 + A22*R22;

        float j00 = fx / tzs, j02 = -fx * txtz / tzs;
        float j11 = fy / tzs, j12 = -fy * tytz / tzs;
        float u0 = j00*C00 + j02*C02;
        float u1 = j00*C01 + j02*C12;
        float u2 = j00*C02 + j02*C22;
        float w1 = j11*C11 + j12*C12;
        float w2 = j11*C12 + j12*C22;
        float cov00 = u0*j00 + u2*j02;
        float cov01 = u1*j11 + u2*j12;
        float cov11 = w1*j11 + w2*j12;

        float a = cov00 + DILATE, b = cov01, c = cov11 + DILATE;
        float det = a*c - b*b;
        if (det == 0.f) det = 1.f;
        float ca = c / det, cb = -b / det, cc = a / det;

        float px = fx * tx / tzs + ((float)IMW - cx) - 0.5f;
        float py = fy * ty / tzs + ((float)IMH - cy) - 0.5f;
        float op = valid ? opac[n] : 0.f;

        // bbox radii of alpha >= 1/255 level set; NaN radii (op<=1/255) -> culled
        float lt = __logf(255.f * op);
        float rx = sqrtf(2.f * lt * a) * 1.0001f + 1e-3f;
        float ry = sqrtf(2.f * lt * c) * 1.0001f + 1e-3f;

        a0 = make_float4(px, py, ca, cb);
        a1 = make_float4(cc, op, tz, __int_as_float(n));
        cu = make_float4(px, py, rx, ry);
    }

    // ---- rank: warp w counts its 64-key range for element 'lane' ----
    const unsigned long long ke = sk[ebase + lane];
    int cnt = 0;
    const int kbase = w * KRANGE;
#pragma unroll 16
    for (int s = 0; s < KRANGE; s++)
        cnt += (sk[kbase + s] < ke) ? 1 : 0;
    scnt2[lane][w] = cnt;            // non-atomic, disjoint per (lane, w)
    __syncthreads();

    // ---- reduce partial counts + scatter directly from registers ----
    if (t < EPC) {
        int r = 0;
#pragma unroll
        for (int ww = 0; ww < PWARPS; ww++) r += scnt2[t][ww];
        g_sorted[v][r][0] = a0;
        g_sorted[v][r][1] = a1;
        g_cull  [v][r]    = cu;
    }
}

// ---------------------------------------------------------------------------
// Phase 2: transmit — cull + compaction (persisted), per-pixel segment
// transmittance. Also zeroes the output chunkwise (blend atomics depend on it).
// ---------------------------------------------------------------------------
__global__ void __launch_bounds__(64) transmit(float* __restrict__ out, int out_count)
{
    const int vz   = blockIdx.z;
    const int v    = vz / NSEG, seg = vz % NSEG;
    const int tile = blockIdx.y * NTILEX + blockIdx.x;
    const int ix   = blockIdx.x * 8 + threadIdx.x;
    const int iy   = blockIdx.y * 8 + threadIdx.y;
    const int tid  = threadIdx.y * 8 + threadIdx.x;
    const int wid  = tid >> 5, lane = tid & 31;
    const float X = (float)ix, Y = (float)iy;
    const float xmin = (float)(blockIdx.x * 8), xmax = xmin + 7.0f;
    const float ymin = (float)(blockIdx.y * 8), ymax = ymin + 7.0f;
    const unsigned lmask = (1u << lane) - 1u;

    // ---- zero my chunk of the output ----
    {
        const int ngrid = NTILE * NVIEW * NSEG;
        const int chunk = (out_count + ngrid - 1) / ngrid;
        const int base  = (vz * NTILE + tile) * chunk;
        for (int i = tid; i < chunk; i += 64) {
            int o = base + i;
            if (o < out_count) out[o] = 0.f;
        }
    }

    __shared__ float4 s0[BATCH + 4], s1[BATCH + 4];
    __shared__ unsigned sball[8];

    // ---- cull the single 256-gaussian batch of this segment ----
    const int base = seg * SEGLEN;
    float4 cd[4];
#pragma unroll
    for (int k = 0; k < 4; k++) cd[k] = g_cull[v][base + k * 64 + tid];

    bool hit[4];
    unsigned myb[4];
#pragma unroll
    for (int k = 0; k < 4; k++) {
        // NaN-safe: any NaN -> false -> culled
        hit[k] = (cd[k].x - cd[k].z <= xmax) && (cd[k].x + cd[k].z >= xmin) &&
                 (cd[k].y - cd[k].w <= ymax) && (cd[k].y + cd[k].w >= ymin);
        myb[k] = __ballot_sync(0xffffffffu, hit[k]);
    }
    if (lane == 0) {
#pragma unroll
        for (int k = 0; k < 4; k++) sball[k * 2 + wid] = myb[k];
    }
    __syncthreads();

    unsigned bl[8];
    int total = 0;
#pragma unroll
    for (int i = 0; i < 8; i++) { bl[i] = sball[i]; total += __popc(bl[i]); }

#pragma unroll
    for (int k = 0; k < 4; k++) {
        if (hit[k]) {
            int ord = k * 2 + wid;
            int off = 0;
            for (int i = 0; i < ord; i++) off += __popc(bl[i]);
            off += __popc(myb[k] & lmask);
            int g = base + k * 64 + tid;
            s0[off] = g_sorted[v][g][0];
            s1[off] = g_sorted[v][g][1];
        }
    }
    // pad to multiple of 4 with inert dummies (op=0 -> alpha 0)
    int pad = (4 - (total & 3)) & 3;
    if (tid < pad) {
        s0[total + tid] = make_float4(0.f, 0.f, 0.f, 0.f);
        s1[total + tid] = make_float4(0.f, 0.f, 0.f, 0.f);
    }
    const int totalp = total + pad;
    __syncthreads();

    // ---- persist compacted list for blend ----
    for (int i = tid; i < totalp; i += 64) {
        g_list0[v][seg][tile][i] = s0[i];
        g_list1[v][seg][tile][i] = s1[i];
    }
    if (tid == 0) g_cnt[v][seg][tile] = totalp;

    // ---- per-pixel transmittance ----
    float T = 1.f;
    for (int j = 0; j < totalp; j += 4) {
#pragma unroll
        for (int u = 0; u < 4; u++) {
            float4 A = s0[j + u];
            float4 B = s1[j + u];
            float dx = X - A.x, dy = Y - A.y;
            float power = -0.5f * (A.z * dx * dx + B.x * dy * dy) - A.w * dx * dy;
            float al = fminf(0.99f, B.y * __expf(power));
            bool skip = (power > 0.f) || !(al >= ALPHA_MIN);
            T *= skip ? 1.f : (1.f - al);
        }
        // safe early out: recorded T >= true T but <= 1e-8 << T_EPS, so any
        // downstream prefix containing this factor still fails the gate.
        if (__all_sync(0xffffffffu, T < 1e-8f)) break;
    }
    g_T[v][seg][iy * IMW + ix] = T;
}

// ---------------------------------------------------------------------------
// Phase 3: blend — gated color accumulation from the precompacted list.
// Channel-split: grid z = (v*NSEG+seg)*2 + half; each CTA does 16 channels.
// ---------------------------------------------------------------------------
__global__ void __launch_bounds__(64) blend(const float* __restrict__ colors,
                                            float* __restrict__ out)
{
    const int vzh  = blockIdx.z;
    const int half = vzh & 1;
    const int vz   = vzh >> 1;
    const int v    = vz / NSEG, seg = vz % NSEG;
    const int tile = blockIdx.y * NTILEX + blockIdx.x;
    const int ix   = blockIdx.x * 8 + threadIdx.x;
    const int iy   = blockIdx.y * 8 + threadIdx.y;
    const int tid  = threadIdx.y * 8 + threadIdx.x;
    const int pix  = iy * IMW + ix;
    const float X = (float)ix, Y = (float)iy;

    float T = 1.f;
#pragma unroll
    for (int s = 0; s < NSEG - 1; s++)
        if (s < seg) T *= g_T[v][s][pix];

    // whole-CTA skip: every weight in this segment would be gated to 0
    if (__syncthreads_and(T < T_EPS)) return;

    const int cnt = g_cnt[v][seg][tile];

    __shared__ float4 s0[SEGLEN + 4], s1[SEGLEN + 4];
    for (int i = tid; i < cnt; i += 64) {
        s0[i] = g_list0[v][seg][tile][i];
        s1[i] = g_list1[v][seg][tile][i];
    }
    __syncthreads();

    float acc[16];
#pragma unroll
    for (int c = 0; c < 16; c++) acc[c] = 0.f;
    float dacc = 0.f;
    bool applied = false;

    for (int j = 0; j < cnt; j += 4) {
        float w4[4], tz4[4];
        int   id4[4];
#pragma unroll
        for (int u = 0; u < 4; u++) {
            float4 A = s0[j + u];
            float4 B = s1[j + u];
            float dx = X - A.x, dy = Y - A.y;
            float power = -0.5f * (A.z * dx * dx + B.x * dy * dy) - A.w * dx * dy;
            float al = fminf(0.99f, B.y * __expf(power));
            bool skip = (power > 0.f) || !(al >= ALPHA_MIN);
            float ale = skip ? 0.f : al;
            float Tn  = T * (1.f - ale);
            w4[u]  = (Tn >= T_EPS) ? ale * T : 0.f;
            tz4[u] = B.z;
            id4[u] = __float_as_int(B.w);
            T = Tn;
        }
#pragma unroll
        for (int u = 0; u < 4; u++) {
            if (w4[u] != 0.f) {
                applied = true;
                float w = w4[u];
                const float4* crow = (const float4*)
                    (colors + (size_t)((unsigned)id4[u]) * NCH + half * 16);
#pragma unroll
                for (int c4 = 0; c4 < 4; c4++) {
                    float4 cv = crow[c4];
                    acc[c4*4+0] += w * cv.x;
                    acc[c4*4+1] += w * cv.y;
                    acc[c4*4+2] += w * cv.z;
                    acc[c4*4+3] += w * cv.w;
                }
                dacc += w * tz4[u];
            }
        }
        if (__all_sync(0xffffffffu, T < T_EPS)) break;   // per-warp; no smem reuse
    }

    if (applied) {
#pragma unroll
        for (int c = 0; c < 16; c++)
            atomicAdd(&out[(size_t)(v * NCH + half * 16 + c) * NPIX + pix], acc[c]);
        if (half == 0)
            atomicAdd(&out[(size_t)NVIEW * NCH * NPIX + (size_t)v * NPIX + pix], dacc);
    }
}

// ---------------------------------------------------------------------------
extern "C" void kernel_launch(void* const* d_in, const int* in_sizes, int n_in,
                              void* d_out, int out_size)
{
    const float* means   = (const float*)d_in[0];
    const float* colors  = (const float*)d_in[1];
    const float* opac    = (const float*)d_in[2];
    const float* scales  = (const float*)d_in[3];
    const float* rots    = (const float*)d_in[4];
    const float* cam2img = (const float*)d_in[5];
    const float* cam2ego = (const float*)d_in[6];
    float* out = (float*)d_out;

    prep    <<<dim3(NVIEW, NGAUSS / EPC), 1024>>>(means, opac, scales, rots, cam2img, cam2ego);
    transmit<<<dim3(NTILEX, NTILEY, NVIEW * NSEG), dim3(8, 8)>>>(out, out_size);
    blend   <<<dim3(NTILEX, NTILEY, NVIEW * NSEG * 2), dim3(8, 8)>>>(colors, out);
}